// round 16
// baseline (speedup 1.0000x reference)
#include <cuda_runtime.h>

// VDDecoder: 3-layer LSTM stack (H=2,2,1), locked dropout between layers.
// R16 = R15 (one hidden unit per lane; 5-lane groups L1u0,L1u1,L2u0,L2u1,L3;
// 2-deep inter-layer stagger; masks folded into input weights; f32x2 gate
// pairs; block=64) with the x prefetch restructured so the LDG destination IS
// the register consumed 4 iterations later (consume XREG, then XREG = *xr
// directly; no end-of-iteration copy). This guarantees the long-scoreboard
// wait lands ~4 iterations (~1000 cyc) after issue, hiding DRAM latency.

typedef unsigned long long u64;

__device__ __forceinline__ float ftanh(float x) {
    float r; asm("tanh.approx.f32 %0, %1;" : "=f"(r) : "f"(x)); return r;
}
__device__ __forceinline__ u64 fpk(float lo, float hi) {
    u64 d; asm("mov.b64 %0, {%1, %2};" : "=l"(d) : "f"(lo), "f"(hi)); return d;
}
__device__ __forceinline__ u64 fpk2(float v) { return fpk(v, v); }
__device__ __forceinline__ void funp(u64 v, float& lo, float& hi) {
    asm("mov.b64 {%0, %1}, %2;" : "=f"(lo), "=f"(hi) : "l"(v));
}
__device__ __forceinline__ u64 ffma2(u64 a, u64 b, u64 c) {
    u64 d; asm("fma.rn.f32x2 %0, %1, %2, %3;" : "=l"(d) : "l"(a), "l"(b), "l"(c)); return d;
}

extern "C" __global__ void __launch_bounds__(64, 1)
vdlstm_v12_kernel(const float* __restrict__ x,
                  const float* __restrict__ W1ih, const float* __restrict__ W1hh,
                  const float* __restrict__ b1,   const float* __restrict__ m1,
                  const float* __restrict__ W2ih, const float* __restrict__ W2hh,
                  const float* __restrict__ b2,   const float* __restrict__ m2,
                  const float* __restrict__ W3ih, const float* __restrict__ W3hh,
                  const float* __restrict__ b3,   const float* __restrict__ m3,
                  float* __restrict__ out, int T, int B)
{
    const int lane = threadIdx.x & 31;
    const int gw   = blockIdx.x * (blockDim.x >> 5) + (threadIdx.x >> 5);
    const int grp  = lane / 5;                  // 0..6 (grp 6 = lanes 30,31)
    const int sub  = lane - grp * 5;            // 0..4 role
    const int base = grp * 5;
    int e = gw * 6 + grp;
    if (e > B - 1) e = B - 1;

    const int layer = (sub <= 1) ? 0 : (sub <= 3) ? 1 : 2;
    const int unit  = (sub == 1 || sub == 3) ? 1 : 0;

    const int sibsrc = (sub == 4) ? lane : (base + (sub ^ 1));
    const int p0src  = (layer == 2) ? (base + 2) : base;
    const int p1src  = (layer == 2) ? (base + 3) : (base + 1);

    // ---- per-lane scalar weights, fold masks, pack gate pairs ----
    float wa0[4], wa1[4], who[4], whs[4], bq[4];
#pragma unroll
    for (int q = 0; q < 4; q++) {
        float s = (q == 2) ? 1.0f : 0.5f;
        if (layer == 0) {
            int row = 2 * q + unit;
            wa0[q] = W1ih[row] * s;
            wa1[q] = 0.f;
            who[q] = W1hh[2 * row + unit] * s;
            whs[q] = W1hh[2 * row + (1 - unit)] * s;
            bq[q]  = b1[row] * s;
        } else if (layer == 1) {
            int row = 2 * q + unit;
            wa0[q] = W2ih[2 * row + 0] * s;
            wa1[q] = W2ih[2 * row + 1] * s;
            who[q] = W2hh[2 * row + unit] * s;
            whs[q] = W2hh[2 * row + (1 - unit)] * s;
            bq[q]  = b2[row] * s;
        } else {
            wa0[q] = W3ih[2 * q + 0] * s;
            wa1[q] = W3ih[2 * q + 1] * s;
            who[q] = W3hh[q] * s;
            whs[q] = 0.f;
            bq[q]  = b3[q] * s;
        }
    }
    {
        float am0 = 1.f, am1 = 1.f;
        if (layer == 1) { am0 = m1[2 * e + 0]; am1 = m1[2 * e + 1]; }
        if (layer == 2) { am0 = m2[2 * e + 0]; am1 = m2[2 * e + 1]; }
#pragma unroll
        for (int q = 0; q < 4; q++) { wa0[q] *= am0; wa1[q] *= am1; }
    }
    const float m30 = m3[e];

    u64 Pa0[2], Pa1[2], Pho[2], Phs[2], Pb[2];
#pragma unroll
    for (int P = 0; P < 2; P++) {
        Pa0[P] = fpk(wa0[2 * P], wa0[2 * P + 1]);
        Pa1[P] = fpk(wa1[2 * P], wa1[2 * P + 1]);
        Pho[P] = fpk(who[2 * P], who[2 * P + 1]);
        Phs[P] = fpk(whs[2 * P], whs[2 * P + 1]);
        Pb[P]  = fpk(bq[2 * P],  bq[2 * P + 1]);
    }

    // ---- state ----
    float h = 0.f, c = 0.f;
    float hs = 0.f;
    float rA0 = 0.f, rA1 = 0.f;
    float rB0 = 0.f, rB1 = 0.f;

    const float* xp = x + e;
    const long long Bs = (long long)B;
    const unsigned FULL = 0xffffffffu;

    auto stepU = [&](float a0, float a1, float& nh, float& nc) {
        u64 a0b = fpk2(a0), a1b = fpk2(a1), hb = fpk2(h), hsb = fpk2(hs);
        u64 gP0 = ffma2(hb, Pho[0], ffma2(hsb, Phs[0], ffma2(a1b, Pa1[0], ffma2(a0b, Pa0[0], Pb[0]))));
        u64 gP1 = ffma2(hb, Pho[1], ffma2(hsb, Phs[1], ffma2(a1b, Pa1[1], ffma2(a0b, Pa0[1], Pb[1]))));
        float g0, g1, g2, g3;
        funp(gP0, g0, g1);
        funp(gP1, g2, g3);
        float t0 = ftanh(g0), t1 = ftanh(g1), t2 = ftanh(g2), t3 = ftanh(g3);
        float ig = fmaf(t0, 0.5f, 0.5f);
        float fg = fmaf(t1, 0.5f, 0.5f);
        float og = fmaf(t3, 0.5f, 0.5f);
        nc = fmaf(fg, c, ig * t2);
        nh = og * ftanh(nc);
    };

    auto exch = [&]() {
        float s_sib = __shfl_sync(FULL, h, sibsrc);
        float s_p0  = __shfl_sync(FULL, h, p0src);
        float s_p1  = __shfl_sync(FULL, h, p1src);
        hs  = s_sib;
        rA0 = rB0; rA1 = rB1;
        rB0 = s_p0; rB1 = s_p1;
    };

    // ---- prologue: u = 0..3; layer l first commits at u = 2l ----
    for (int u = 0; u < 4; ++u) {
        float xcur = xp[(long long)u * Bs];
        float a0 = (layer == 0) ? xcur : rA0;
        float a1 = rA1;
        float nh, nc;
        stepU(a0, a1, nh, nc);
        if (u >= 2 * layer) { h = nh; c = nc; }
        exch();
    }

    // ---- steady state: u = 4 .. T+3; layer l works time u-2l; L3 stores row u-4 ----
    float xa = xp[4 * Bs], xb = xp[5 * Bs], xc = xp[6 * Bs], xd = xp[7 * Bs];

    const float* xr    = xp + 8 * Bs;                 // prefetch row u+4 (u=4)
    const float* xlast = xp + (long long)(T - 1) * Bs;
    float* orow = out + e;                            // row u-4 = 0 at u=4

    int u = 4;

    // Consume XREG (row uu), then load row uu+4 DIRECTLY into XREG: the LDG
    // wait lands at XREG's next read, 4 iterations later.
#define V12_MAIN(XREG)                                                         \
    {                                                                          \
        float a0 = (layer == 0) ? XREG : rA0;                                  \
        float a1 = rA1;                                                        \
        XREG = *xr; xr += Bs;                                                  \
        float nh, nc;                                                          \
        stepU(a0, a1, nh, nc);                                                 \
        h = nh; c = nc;                                                        \
        exch();                                                                \
        if (sub == 4) *orow = h * m30;                                         \
        orow += Bs;                                                            \
    }

    for (; u + 3 <= T - 5; u += 4) {
        V12_MAIN(xa)
        V12_MAIN(xb)
        V12_MAIN(xc)
        V12_MAIN(xd)
    }
#undef V12_MAIN

    // tail: clamped prefetch; runs through u = T+3 (emits rows .. T-1)
    for (; u < T + 4; ++u) {
        const float* xq = (xr > xlast) ? xlast : xr;
        float nx = *xq; xr += Bs;
        float a0 = (layer == 0) ? xa : rA0;
        float a1 = rA1;
        float nh, nc;
        stepU(a0, a1, nh, nc);
        h = nh; c = nc;
        exch();
        if (sub == 4) *orow = h * m30;
        orow += Bs;
        xa = xb; xb = xc; xc = xd; xd = nx;
    }
}

extern "C" void kernel_launch(void* const* d_in, const int* in_sizes, int n_in,
                              void* d_out, int out_size)
{
    const float* x    = (const float*)d_in[0];
    const float* W1ih = (const float*)d_in[1];
    const float* W1hh = (const float*)d_in[2];
    const float* b1   = (const float*)d_in[3];
    const float* m1   = (const float*)d_in[4];
    const float* W2ih = (const float*)d_in[5];
    const float* W2hh = (const float*)d_in[6];
    const float* b2   = (const float*)d_in[7];
    const float* m2   = (const float*)d_in[8];
    const float* W3ih = (const float*)d_in[9];
    const float* W3hh = (const float*)d_in[10];
    const float* b3   = (const float*)d_in[11];
    const float* m3   = (const float*)d_in[12];

    int B = in_sizes[12];            // m3 is [B]
    int T = in_sizes[0] / B;         // x is [T, B, 1]

    int warps   = (B + 5) / 6;       // 6 elements per warp
    int threads = 64;                // 2 warps per block
    int blocks  = (warps + 1) / 2;
    vdlstm_v12_kernel<<<blocks, threads>>>(x, W1ih, W1hh, b1, m1,
                                           W2ih, W2hh, b2, m2,
                                           W3ih, W3hh, b3, m3,
                                           (float*)d_out, T, B);
}

// round 17
// speedup vs baseline: 1.3671x; 1.3671x over previous
#include <cuda_runtime.h>

// VDDecoder: 3-layer LSTM stack (H=2,2,1), locked dropout between layers.
// R17 = R15 exactly (one hidden unit per lane; 5-lane groups L1u0,L1u1,L2u0,
// L2u1,L3; 2-deep inter-layer stagger; masks folded into input weights; f32x2
// gate pairs; block=64) with the steady-state loop unrolled 8x (8 prefetch
// registers, distance 8) to halve branch overhead and widen the scheduler's
// straight-line window.

typedef unsigned long long u64;

__device__ __forceinline__ float ftanh(float x) {
    float r; asm("tanh.approx.f32 %0, %1;" : "=f"(r) : "f"(x)); return r;
}
__device__ __forceinline__ u64 fpk(float lo, float hi) {
    u64 d; asm("mov.b64 %0, {%1, %2};" : "=l"(d) : "f"(lo), "f"(hi)); return d;
}
__device__ __forceinline__ u64 fpk2(float v) { return fpk(v, v); }
__device__ __forceinline__ void funp(u64 v, float& lo, float& hi) {
    asm("mov.b64 {%0, %1}, %2;" : "=f"(lo), "=f"(hi) : "l"(v));
}
__device__ __forceinline__ u64 ffma2(u64 a, u64 b, u64 c) {
    u64 d; asm("fma.rn.f32x2 %0, %1, %2, %3;" : "=l"(d) : "l"(a), "l"(b), "l"(c)); return d;
}

extern "C" __global__ void __launch_bounds__(64, 1)
vdlstm_v13_kernel(const float* __restrict__ x,
                  const float* __restrict__ W1ih, const float* __restrict__ W1hh,
                  const float* __restrict__ b1,   const float* __restrict__ m1,
                  const float* __restrict__ W2ih, const float* __restrict__ W2hh,
                  const float* __restrict__ b2,   const float* __restrict__ m2,
                  const float* __restrict__ W3ih, const float* __restrict__ W3hh,
                  const float* __restrict__ b3,   const float* __restrict__ m3,
                  float* __restrict__ out, int T, int B)
{
    const int lane = threadIdx.x & 31;
    const int gw   = blockIdx.x * (blockDim.x >> 5) + (threadIdx.x >> 5);
    const int grp  = lane / 5;                  // 0..6 (grp 6 = lanes 30,31)
    const int sub  = lane - grp * 5;            // 0..4 role
    const int base = grp * 5;
    int e = gw * 6 + grp;
    if (e > B - 1) e = B - 1;

    const int layer = (sub <= 1) ? 0 : (sub <= 3) ? 1 : 2;
    const int unit  = (sub == 1 || sub == 3) ? 1 : 0;

    const int sibsrc = (sub == 4) ? lane : (base + (sub ^ 1));
    const int p0src  = (layer == 2) ? (base + 2) : base;
    const int p1src  = (layer == 2) ? (base + 3) : (base + 1);

    // ---- per-lane scalar weights, fold masks, pack gate pairs ----
    float wa0[4], wa1[4], who[4], whs[4], bq[4];
#pragma unroll
    for (int q = 0; q < 4; q++) {
        float s = (q == 2) ? 1.0f : 0.5f;
        if (layer == 0) {
            int row = 2 * q + unit;
            wa0[q] = W1ih[row] * s;
            wa1[q] = 0.f;
            who[q] = W1hh[2 * row + unit] * s;
            whs[q] = W1hh[2 * row + (1 - unit)] * s;
            bq[q]  = b1[row] * s;
        } else if (layer == 1) {
            int row = 2 * q + unit;
            wa0[q] = W2ih[2 * row + 0] * s;
            wa1[q] = W2ih[2 * row + 1] * s;
            who[q] = W2hh[2 * row + unit] * s;
            whs[q] = W2hh[2 * row + (1 - unit)] * s;
            bq[q]  = b2[row] * s;
        } else {
            wa0[q] = W3ih[2 * q + 0] * s;
            wa1[q] = W3ih[2 * q + 1] * s;
            who[q] = W3hh[q] * s;
            whs[q] = 0.f;
            bq[q]  = b3[q] * s;
        }
    }
    {
        float am0 = 1.f, am1 = 1.f;
        if (layer == 1) { am0 = m1[2 * e + 0]; am1 = m1[2 * e + 1]; }
        if (layer == 2) { am0 = m2[2 * e + 0]; am1 = m2[2 * e + 1]; }
#pragma unroll
        for (int q = 0; q < 4; q++) { wa0[q] *= am0; wa1[q] *= am1; }
    }
    const float m30 = m3[e];

    u64 Pa0[2], Pa1[2], Pho[2], Phs[2], Pb[2];
#pragma unroll
    for (int P = 0; P < 2; P++) {
        Pa0[P] = fpk(wa0[2 * P], wa0[2 * P + 1]);
        Pa1[P] = fpk(wa1[2 * P], wa1[2 * P + 1]);
        Pho[P] = fpk(who[2 * P], who[2 * P + 1]);
        Phs[P] = fpk(whs[2 * P], whs[2 * P + 1]);
        Pb[P]  = fpk(bq[2 * P],  bq[2 * P + 1]);
    }

    // ---- state ----
    float h = 0.f, c = 0.f;
    float hs = 0.f;
    float rA0 = 0.f, rA1 = 0.f;
    float rB0 = 0.f, rB1 = 0.f;

    const float* xp = x + e;
    const long long Bs = (long long)B;
    const unsigned FULL = 0xffffffffu;

    auto stepU = [&](float a0, float a1, float& nh, float& nc) {
        u64 a0b = fpk2(a0), a1b = fpk2(a1), hb = fpk2(h), hsb = fpk2(hs);
        u64 gP0 = ffma2(hb, Pho[0], ffma2(hsb, Phs[0], ffma2(a1b, Pa1[0], ffma2(a0b, Pa0[0], Pb[0]))));
        u64 gP1 = ffma2(hb, Pho[1], ffma2(hsb, Phs[1], ffma2(a1b, Pa1[1], ffma2(a0b, Pa0[1], Pb[1]))));
        float g0, g1, g2, g3;
        funp(gP0, g0, g1);
        funp(gP1, g2, g3);
        float t0 = ftanh(g0), t1 = ftanh(g1), t2 = ftanh(g2), t3 = ftanh(g3);
        float ig = fmaf(t0, 0.5f, 0.5f);
        float fg = fmaf(t1, 0.5f, 0.5f);
        float og = fmaf(t3, 0.5f, 0.5f);
        nc = fmaf(fg, c, ig * t2);
        nh = og * ftanh(nc);
    };

    auto exch = [&]() {
        float s_sib = __shfl_sync(FULL, h, sibsrc);
        float s_p0  = __shfl_sync(FULL, h, p0src);
        float s_p1  = __shfl_sync(FULL, h, p1src);
        hs  = s_sib;
        rA0 = rB0; rA1 = rB1;
        rB0 = s_p0; rB1 = s_p1;
    };

    // ---- prologue: u = 0..3; layer l first commits at u = 2l ----
    for (int u = 0; u < 4; ++u) {
        float xcur = xp[(long long)u * Bs];
        float a0 = (layer == 0) ? xcur : rA0;
        float a1 = rA1;
        float nh, nc;
        stepU(a0, a1, nh, nc);
        if (u >= 2 * layer) { h = nh; c = nc; }
        exch();
    }

    // ---- steady state: u = 4 .. T+3; layer l works time u-2l; L3 stores row u-4 ----
    const float* xlast = xp + (long long)(T - 1) * Bs;

    // initial prefetch of rows u..u+7 = 4..11 (clamped for safety)
    float xv[8];
#pragma unroll
    for (int k = 0; k < 8; k++) {
        int idx = (4 + k < T) ? (4 + k) : (T - 1);
        xv[k] = xp[(long long)idx * Bs];
    }
    const float* xr = xp + 12 * Bs;               // next prefetch row (u+8 at u=4)
    float* orow = out + e;                        // row u-4 = 0 at u=4

    int u = 4;

#define V13_MAIN(K)                                                            \
    {                                                                          \
        float nx = *xr; xr += Bs;                                              \
        float a0 = (layer == 0) ? xv[K] : rA0;                                 \
        float a1 = rA1;                                                        \
        float nh, nc;                                                          \
        stepU(a0, a1, nh, nc);                                                 \
        h = nh; c = nc;                                                        \
        exch();                                                                \
        if (sub == 4) *orow = h * m30;                                         \
        orow += Bs;                                                            \
        xv[K] = nx;                                                            \
    }

    // main loop: prefetch row u+7+8 <= T-1  ->  u <= T-16
    for (; u + 15 <= T - 1; u += 8) {
        V13_MAIN(0)
        V13_MAIN(1)
        V13_MAIN(2)
        V13_MAIN(3)
        V13_MAIN(4)
        V13_MAIN(5)
        V13_MAIN(6)
        V13_MAIN(7)
    }
#undef V13_MAIN

    // tail: clamped prefetch; runs through u = T+3 (emits rows .. T-1)
    for (; u < T + 4; ++u) {
        const float* xq = (xr > xlast) ? xlast : xr;
        float nx = *xq; xr += Bs;
        float a0 = (layer == 0) ? xv[0] : rA0;
        float a1 = rA1;
        float nh, nc;
        stepU(a0, a1, nh, nc);
        h = nh; c = nc;
        exch();
        if (sub == 4) *orow = h * m30;
        orow += Bs;
#pragma unroll
        for (int k = 0; k < 7; k++) xv[k] = xv[k + 1];
        xv[7] = nx;
    }
}

extern "C" void kernel_launch(void* const* d_in, const int* in_sizes, int n_in,
                              void* d_out, int out_size)
{
    const float* x    = (const float*)d_in[0];
    const float* W1ih = (const float*)d_in[1];
    const float* W1hh = (const float*)d_in[2];
    const float* b1   = (const float*)d_in[3];
    const float* m1   = (const float*)d_in[4];
    const float* W2ih = (const float*)d_in[5];
    const float* W2hh = (const float*)d_in[6];
    const float* b2   = (const float*)d_in[7];
    const float* m2   = (const float*)d_in[8];
    const float* W3ih = (const float*)d_in[9];
    const float* W3hh = (const float*)d_in[10];
    const float* b3   = (const float*)d_in[11];
    const float* m3   = (const float*)d_in[12];

    int B = in_sizes[12];            // m3 is [B]
    int T = in_sizes[0] / B;         // x is [T, B, 1]

    int warps   = (B + 5) / 6;       // 6 elements per warp
    int threads = 64;                // 2 warps per block
    int blocks  = (warps + 1) / 2;
    vdlstm_v13_kernel<<<blocks, threads>>>(x, W1ih, W1hh, b1, m1,
                                           W2ih, W2hh, b2, m2,
                                           W3ih, W3hh, b3, m3,
                                           (float*)d_out, T, B);
}